// round 11
// baseline (speedup 1.0000x reference)
#include <cuda_runtime.h>
#include <cstdint>

#define NQ     6
#define BATCH  256
#define SEQ    512
#define FULLM  0xffffffffu
#define PI_F   3.14159265358979323846f
#define SH(v,m) __shfl_xor_sync(FULLM, (v), (m))

// ---------------- scratch ----------------
__device__ float4 g_pk [BATCH * SEQ * 3];    // [dta0..3][dta4,5,xdt0,1][xdt2..5]
__device__ float4 g_ph [BATCH * SEQ * 32];   // per-lane QSVT phase (c0,s0,c1,s1), 64MB
__device__ float4 g_cs6[BATCH * SEQ * 3];    // fold sincos pairs (c,s)x6
__device__ float  g_cw [BATCH * SEQ * 18];
__device__ float  g_B  [32 * 12];            // per-lane B0[6],B1[6]
__device__ float  g_tf [24];
__device__ float2 g_fa [12];
__device__ float2 g_fb [12];
__device__ float2 g_crx[24];

// ---------------- prep 1 ----------------
__global__ void prep_kernel(const float* __restrict__ angles,
                            const float* __restrict__ Wx,
                            const float* __restrict__ Wdt,
                            const float* __restrict__ bdt,
                            const float* __restrict__ Wc) {
    int idx = blockIdx.x * blockDim.x + threadIdx.x;
    if (idx >= BATCH * SEQ) return;
    float a[6];
#pragma unroll
    for (int k = 0; k < 6; ++k) a[k] = angles[idx * 6 + k];
    float dtr[3];
#pragma unroll
    for (int r = 0; r < 3; ++r) {
        float s = 0.f;
#pragma unroll
        for (int k = 0; k < 6; ++k) s += a[k] * Wx[r * 6 + k];
        dtr[r] = s;
    }
    float C[6];
#pragma unroll
    for (int j = 0; j < 6; ++j) {
        float s = 0.f;
#pragma unroll
        for (int k = 0; k < 6; ++k) s += a[k] * Wx[(9 + j) * 6 + k];
        C[j] = s;
    }
    float dta[6];
#pragma unroll
    for (int i = 0; i < 6; ++i) {
        float v = bdt[i];
#pragma unroll
        for (int r = 0; r < 3; ++r) v += dtr[r] * Wdt[i * 3 + r];
        float sp = (v > 20.f) ? v : log1pf(expf(v));
        dta[i] = tanhf(sp) * PI_F;
    }
    g_pk[idx * 3 + 0] = make_float4(dta[0], dta[1], dta[2], dta[3]);
    g_pk[idx * 3 + 1] = make_float4(dta[4], dta[5], 0.f, 0.f);
    float c6[6], s6[6];
#pragma unroll
    for (int i = 0; i < 6; ++i) __sincosf(a[i] * dta[i], &s6[i], &c6[i]);
    g_cs6[idx * 3 + 0] = make_float4(c6[0], s6[0], c6[1], s6[1]);
    g_cs6[idx * 3 + 1] = make_float4(c6[2], s6[2], c6[3], s6[3]);
    g_cs6[idx * 3 + 2] = make_float4(c6[4], s6[4], c6[5], s6[5]);
#pragma unroll
    for (int j = 0; j < 18; ++j) {
        float s = 0.f;
#pragma unroll
        for (int k = 0; k < 6; ++k) s += C[k] * Wc[j * 6 + k];
        g_cw[idx * 18 + j] = s;
    }
}

// ---------------- prep 2: tables + per-lane QSVT coefficients ----------------
__global__ void prep2_kernel(const float* __restrict__ pc,
                             const float* __restrict__ qp,
                             const float* __restrict__ cp) {
    int t = threadIdx.x;
    if (t < 24) {
        int d = t / 6, i = t % 6;
        g_tf[t] = pc[d] * PI_F * ((d < 3) ? qp[d * 6 + i] : 1.0f);
    }
    if (t < 24) {
        int L = t / 12, k = t % 12;
        float ang = (k < 6) ? cp[L * 30 + 18 + k] : cp[L * 30 + 24 + (k - 6)];
        float th = 0.5f * ang;
        g_crx[t] = make_float2(cosf(th), sinf(th));
    }
    if (t < 12) {
        int L = t / 6, i = t % 6, base = L * 30 + i * 3;
        float cx = cosf(0.5f * cp[base]),     sx = sinf(0.5f * cp[base]);
        float cy = cosf(0.5f * cp[base + 1]), sy = sinf(0.5f * cp[base + 1]);
        float cz = cosf(0.5f * cp[base + 2]), sz = sinf(0.5f * cp[base + 2]);
        float M00r = cy * cx, M00i = sy * sx;
        float M10r = sy * cx, M10i = -cy * sx;
        g_fa[t] = make_float2(cz * M00r + sz * M00i, cz * M00i - sz * M00r);
        g_fb[t] = make_float2(cz * M10r - sz * M10i, cz * M10i + sz * M10r);
    }
    if (t < 32) {   // per-lane B0/B1 (tf computed locally to avoid races)
        int fwd[64];
        for (int s = 0; s < 64; ++s) {
            int q[6];
#pragma unroll
            for (int i = 0; i < 6; ++i) q[i] = (s >> (5 - i)) & 1;
            q[1]^=q[0]; q[2]^=q[1]; q[3]^=q[2]; q[4]^=q[3]; q[5]^=q[4];
            q[0]^=q[5]; q[4]^=q[5]; q[3]^=q[4]; q[2]^=q[3]; q[1]^=q[2]; q[0]^=q[1];
            int tt = 0;
#pragma unroll
            for (int i = 0; i < 6; ++i) tt |= q[i] << (5 - i);
            fwd[s] = tt;
        }
        int inv[64];
        for (int s = 0; s < 64; ++s) inv[fwd[s]] = s;
        float B0[6] = {0,0,0,0,0,0}, B1[6] = {0,0,0,0,0,0};
        int u0 = t, u1 = t + 32;
        for (int k = 1; k <= 4; ++k) {
            u0 = inv[u0]; u1 = inv[u1];
            int d = 4 - k;
#pragma unroll
            for (int i = 0; i < 6; ++i) {
                float c = 0.5f * pc[d] * PI_F * ((d < 3) ? qp[d * 6 + i] : 1.0f);
                B0[i] += ((u0 >> (5 - i)) & 1) ? c : -c;
                B1[i] += ((u1 >> (5 - i)) & 1) ? c : -c;
            }
        }
#pragma unroll
        for (int i = 0; i < 6; ++i) {
            g_B[t * 12 + i]     = B0[i];
            g_B[t * 12 + 6 + i] = B1[i];
        }
    }
}

// ---------------- prep 3: per-(b,t,lane) QSVT phase sincos ----------------
__global__ void prep3_kernel() {
    int tid = blockIdx.x * blockDim.x + threadIdx.x;
    if (tid >= BATCH * SEQ * 32) return;
    int bt = tid >> 5, lane = tid & 31;
    float4 f0 = g_pk[bt * 3 + 0], f1 = g_pk[bt * 3 + 1];
    float dta[6] = {f0.x, f0.y, f0.z, f0.w, f1.x, f1.y};
    const float* Bl = g_B + lane * 12;
    float acc0 = Bl[0] * dta[0], acc1 = Bl[6] * dta[0];
#pragma unroll
    for (int i = 1; i < 6; ++i) {
        acc0 = fmaf(Bl[i],     dta[i], acc0);
        acc1 = fmaf(Bl[6 + i], dta[i], acc1);
    }
    float c0, s0, c1, s1;
    __sincosf(acc0, &s0, &c0);
    __sincosf(acc1, &s1, &c1);
    g_ph[tid] = make_float4(c0, s0, c1, s1);
}

// ---------------- complex / matrix helpers (prologue only) ----------------
__device__ __forceinline__ float2 cmul2(float2 a, float2 b) {
    return make_float2(a.x*b.x - a.y*b.y, a.x*b.y + a.y*b.x);
}
__device__ __forceinline__ float2 cadd2(float2 a, float2 b) {
    return make_float2(a.x + b.x, a.y + b.y);
}
struct M2 { float2 m[2][2]; };
__device__ __forceinline__ M2 mkT(float2 al, float2 be) {
    M2 t;
    t.m[0][0] = al; t.m[0][1] = make_float2(-be.x, be.y);
    t.m[1][0] = be; t.m[1][1] = make_float2(al.x, -al.y);
    return t;
}
__device__ __forceinline__ M2 mkRX(float c, float s) {
    M2 t;
    t.m[0][0] = make_float2(c, 0.f); t.m[0][1] = make_float2(0.f, -s);
    t.m[1][0] = make_float2(0.f, -s); t.m[1][1] = make_float2(c, 0.f);
    return t;
}
__device__ __forceinline__ void kron4(float2 G[4][4], const M2& A, const M2& B) {
#pragma unroll
    for (int i = 0; i < 2; ++i)
#pragma unroll
    for (int j = 0; j < 2; ++j)
#pragma unroll
    for (int k = 0; k < 2; ++k)
#pragma unroll
    for (int l = 0; l < 2; ++l)
        G[2*i + k][2*j + l] = cmul2(A.m[i][j], B.m[k][l]);
}
__device__ __forceinline__ void ident4(float2 G[4][4]) {
#pragma unroll
    for (int i = 0; i < 4; ++i)
#pragma unroll
    for (int j = 0; j < 4; ++j)
        G[i][j] = make_float2(i == j ? 1.f : 0.f, 0.f);
}
__device__ __forceinline__ void ctrlH_mul(float2 G[4][4], const M2& R) {
#pragma unroll
    for (int c = 0; c < 4; ++c) {
        float2 t2 = G[2][c], t3 = G[3][c];
        G[2][c] = cadd2(cmul2(R.m[0][0], t2), cmul2(R.m[0][1], t3));
        G[3][c] = cadd2(cmul2(R.m[1][0], t2), cmul2(R.m[1][1], t3));
    }
}
__device__ __forceinline__ void ctrlL_mul(float2 G[4][4], const M2& R) {
#pragma unroll
    for (int c = 0; c < 4; ++c) {
        float2 t1 = G[1][c], t3 = G[3][c];
        G[1][c] = cadd2(cmul2(R.m[0][0], t1), cmul2(R.m[0][1], t3));
        G[3][c] = cadd2(cmul2(R.m[1][0], t1), cmul2(R.m[1][1], t3));
    }
}
__device__ __forceinline__ void tgtH_mul(float2 G[4][4], const M2& R) {
#pragma unroll
    for (int c = 0; c < 4; ++c) {
#pragma unroll
        for (int aL = 0; aL < 2; ++aL) {
            float2 t0 = G[aL][c], t1 = G[2 + aL][c];
            G[aL][c]     = cadd2(cmul2(R.m[0][0], t0), cmul2(R.m[0][1], t1));
            G[2 + aL][c] = cadd2(cmul2(R.m[1][0], t0), cmul2(R.m[1][1], t1));
        }
    }
}
__device__ __forceinline__ void tgtL_mul(float2 G[4][4], const M2& R) {
#pragma unroll
    for (int c = 0; c < 4; ++c) {
#pragma unroll
        for (int aH = 0; aH < 2; ++aH) {
            float2 t0 = G[2*aH][c], t1 = G[2*aH + 1][c];
            G[2*aH][c]     = cadd2(cmul2(R.m[0][0], t0), cmul2(R.m[0][1], t1));
            G[2*aH + 1][c] = cadd2(cmul2(R.m[1][0], t0), cmul2(R.m[1][1], t1));
        }
    }
}
__device__ __forceinline__ void extractA(const float2 G[4][4], int bL, float* A, float* B) {
    float2 a0 = bL ? G[1][1] : G[0][0], a1 = bL ? G[1][0] : G[0][1];
    float2 a2 = bL ? G[1][3] : G[0][2], a3 = bL ? G[1][2] : G[0][3];
    A[0]=a0.x; A[1]=a0.y; A[2]=a1.x; A[3]=a1.y; A[4]=a2.x; A[5]=a2.y; A[6]=a3.x; A[7]=a3.y;
    float2 b0 = bL ? G[3][1] : G[2][0], b1 = bL ? G[3][0] : G[2][1];
    float2 b2 = bL ? G[3][3] : G[2][2], b3 = bL ? G[3][2] : G[2][3];
    B[0]=b0.x; B[1]=b0.y; B[2]=b1.x; B[3]=b1.y; B[4]=b2.x; B[5]=b2.y; B[6]=b3.x; B[7]=b3.y;
}
__device__ __forceinline__ void extractP(const float2 G[4][4], int bH, int bL, float* C) {
    int d = 2*bH + bL;
#pragma unroll
    for (int j = 0; j < 4; ++j) {
        float2 c = (d == 0) ? G[0][j] : (d == 1) ? G[1][1^j] : (d == 2) ? G[2][2^j] : G[3][3^j];
        C[2*j] = c.x; C[2*j + 1] = c.y;
    }
}

// ---------------- runtime gate primitives ----------------
__device__ __forceinline__ void applyA(float& r0, float& i0, float& r1, float& i1,
                                       int mL, const float* A, const float* B) {
    float p0 = SH(r0, mL), q0 = SH(i0, mL), p1 = SH(r1, mL), q1 = SH(i1, mL);
    float nr0 = A[0]*r0 - A[1]*i0 + A[2]*p0 - A[3]*q0 + A[4]*r1 - A[5]*i1 + A[6]*p1 - A[7]*q1;
    float ni0 = A[0]*i0 + A[1]*r0 + A[2]*q0 + A[3]*p0 + A[4]*i1 + A[5]*r1 + A[6]*q1 + A[7]*p1;
    float nr1 = B[0]*r0 - B[1]*i0 + B[2]*p0 - B[3]*q0 + B[4]*r1 - B[5]*i1 + B[6]*p1 - B[7]*q1;
    float ni1 = B[0]*i0 + B[1]*r0 + B[2]*q0 + B[3]*p0 + B[4]*i1 + B[5]*r1 + B[6]*q1 + B[7]*p1;
    r0 = nr0; i0 = ni0; r1 = nr1; i1 = ni1;
}
__device__ __forceinline__ void applyP(float& r0, float& i0, float& r1, float& i1,
                                       int mH, int mL, const float* C) {
    const int mHL = mH | mL;
    float Ar0 = SH(r0, mL),  Ai0 = SH(i0, mL),  Ar1 = SH(r1, mL),  Ai1 = SH(i1, mL);
    float Br0 = SH(r0, mH),  Bi0 = SH(i0, mH),  Br1 = SH(r1, mH),  Bi1 = SH(i1, mH);
    float Cr0 = SH(r0, mHL), Ci0 = SH(i0, mHL), Cr1 = SH(r1, mHL), Ci1 = SH(i1, mHL);
    float nr0 = C[0]*r0 - C[1]*i0 + C[2]*Ar0 - C[3]*Ai0 + C[4]*Br0 - C[5]*Bi0 + C[6]*Cr0 - C[7]*Ci0;
    float ni0 = C[0]*i0 + C[1]*r0 + C[2]*Ai0 + C[3]*Ar0 + C[4]*Bi0 + C[5]*Br0 + C[6]*Ci0 + C[7]*Cr0;
    float nr1 = C[0]*r1 - C[1]*i1 + C[2]*Ar1 - C[3]*Ai1 + C[4]*Br1 - C[5]*Bi1 + C[6]*Cr1 - C[7]*Ci1;
    float ni1 = C[0]*i1 + C[1]*r1 + C[2]*Ai1 + C[3]*Ar1 + C[4]*Bi1 + C[5]*Br1 + C[6]*Ci1 + C[7]*Cr1;
    r0 = nr0; i0 = ni0; r1 = nr1; i1 = ni1;
}
__device__ __forceinline__ void crx_cb5(float& r1, float& i1, int m, float c, float s) {
    float p = SH(r1, m), q = SH(i1, m);
    float nr1 = fmaf(s, q, c * r1);
    float ni1 = fmaf(-s, p, c * i1);
    r1 = nr1; i1 = ni1;
}
__device__ __forceinline__ float wsum(float v) {
    v += SH(v, 16); v += SH(v, 8); v += SH(v, 4); v += SH(v, 2); v += SH(v, 1);
    return v;
}

// ---------------- main sim: one warp per chain ----------------
__global__ void __launch_bounds__(32, 1)
sim_kernel(const float* __restrict__ angles,
           const float* __restrict__ Dv_in,
           float* __restrict__ out) {
    const int b    = blockIdx.x;
    const int lane = threadIdx.x;

    // sigma^{-4} source indices (for product-state evaluation)
    int fwd[64];
    for (int s = 0; s < 64; ++s) {
        int q[6];
#pragma unroll
        for (int i = 0; i < 6; ++i) q[i] = (s >> (5 - i)) & 1;
        q[1]^=q[0]; q[2]^=q[1]; q[3]^=q[2]; q[4]^=q[3]; q[5]^=q[4];
        q[0]^=q[5]; q[4]^=q[5]; q[3]^=q[4]; q[2]^=q[3]; q[1]^=q[2]; q[0]^=q[1];
        int tt = 0;
#pragma unroll
        for (int i = 0; i < 6; ++i) tt |= q[i] << (5 - i);
        fwd[s] = tt;
    }
    int inv[64];
    for (int s = 0; s < 64; ++s) inv[fwd[s]] = s;
    int u0 = lane, u1 = lane + 32;
    for (int k = 1; k <= 4; ++k) { u0 = inv[u0]; u1 = inv[u1]; }
    const int s40 = u0, s41 = u1;

    int lbit[5];
#pragma unroll
    for (int bp = 0; bp < 5; ++bp) lbit[bp] = (lane >> bp) & 1;

    // ---- build per-lane block-gate coefficients (one-time) ----
    float Aa[2][8], Ab[2][8], Bc[2][8], Cc[2][8];
    float ACa[2][8], ACb[2][8], B2c[2][8], A2a[2][8], A2b[2][8];
    float C5c[2], C5s[2];
#pragma unroll
    for (int L = 0; L < 2; ++L) {
        M2 T0 = mkT(g_fa[L*6+0], g_fb[L*6+0]);
        M2 T1 = mkT(g_fa[L*6+1], g_fb[L*6+1]);
        M2 T2 = mkT(g_fa[L*6+2], g_fb[L*6+2]);
        M2 T3 = mkT(g_fa[L*6+3], g_fb[L*6+3]);
        M2 T4 = mkT(g_fa[L*6+4], g_fb[L*6+4]);
        M2 T5 = mkT(g_fa[L*6+5], g_fb[L*6+5]);
        float2 cs;
        cs = g_crx[L*12+0];  M2 R01 = mkRX(cs.x, cs.y);
        cs = g_crx[L*12+1];  M2 R12c = mkRX(lbit[4] ? cs.x : 1.f, lbit[4] ? cs.y : 0.f);
        cs = g_crx[L*12+2];  M2 R23 = mkRX(cs.x, cs.y);
        cs = g_crx[L*12+3];  M2 R34c = mkRX(lbit[2] ? cs.x : 1.f, lbit[2] ? cs.y : 0.f);
        cs = g_crx[L*12+4];  M2 R45 = mkRX(cs.x, cs.y);
        cs = g_crx[L*12+5];  M2 R50c = mkRX(lbit[0] ? cs.x : 1.f, lbit[0] ? cs.y : 0.f);
        cs = g_crx[L*12+6];  M2 R54c = mkRX(lbit[0] ? cs.x : 1.f, lbit[0] ? cs.y : 0.f);
        cs = g_crx[L*12+7];  M2 R43c = mkRX(lbit[1] ? cs.x : 1.f, lbit[1] ? cs.y : 0.f);
        cs = g_crx[L*12+8];  M2 R32 = mkRX(cs.x, cs.y);
        cs = g_crx[L*12+9];  M2 R21c = mkRX(lbit[3] ? cs.x : 1.f, lbit[3] ? cs.y : 0.f);
        cs = g_crx[L*12+10]; M2 R10 = mkRX(cs.x, cs.y);
        cs = g_crx[L*12+11]; C5c[L] = cs.x; C5s[L] = cs.y;

        float2 G[4][4];
        kron4(G, T0, T1); ctrlH_mul(G, R01);
        extractA(G, lbit[4], Aa[L], Ab[L]);
        kron4(G, T2, T3); tgtH_mul(G, R12c); ctrlH_mul(G, R23);
        extractP(G, lbit[3], lbit[2], Bc[L]);
        kron4(G, T4, T5); tgtH_mul(G, R34c); ctrlH_mul(G, R45);
        extractP(G, lbit[1], lbit[0], Cc[L]);
        kron4(G, R50c, R54c);
        extractA(G, lbit[1], ACa[L], ACb[L]);
        ident4(G); tgtL_mul(G, R43c); ctrlL_mul(G, R32);
        extractP(G, lbit[3], lbit[2], B2c[L]);
        ident4(G); tgtL_mul(G, R21c); ctrlL_mul(G, R10);
        extractA(G, lbit[4], A2a[L], A2b[L]);
    }

    // zi gather lanes + qubit-select predicates
    int srcZi = 26;
    if (lane == 7)  srcZi = 16;
    if (lane == 8)  srcZi = 24;
    if (lane == 9)  srcZi = 20;
    if (lane == 10) srcZi = 28;
    if (lane == 11) srcZi = 18;
    const int qsel = lane % 6;
    const bool q0 = qsel == 0, q1 = qsel == 1, q2 = qsel == 2, q3 = qsel == 3, q4 = qsel == 4;
#define SEL6(v) (q0 ? v[0] : q1 ? v[1] : q2 ? v[2] : q3 ? v[3] : q4 ? v[4] : v[5])

    float h[6] = {0.f, 0.f, 0.f, 0.f, 0.f, 0.f};
    const float*  angB = angles + (size_t)b * SEQ * 6;
    const float4* phB  = g_ph   + (size_t)b * SEQ * 32;
    const float4* csB  = g_cs6  + (size_t)b * SEQ * 3;
    const float*  cwB  = g_cw   + (size_t)b * SEQ * 18;
    float*        outB = out    + (size_t)b * SEQ * 18;
    const float   Dme  = (lane < 18) ? Dv_in[lane] : 0.f;

    // preload t=0 inputs
    float4 ph = __ldg(phB + lane);
    float4 e0 = __ldg(csB + 0), e1 = __ldg(csB + 1), e2 = __ldg(csB + 2);
    float cwv = (lane < 18) ? __ldg(cwB + lane) : 0.f;
    float xme = (lane < 18) ? __ldg(angB + qsel) : 0.f;

#pragma unroll 1
    for (int t = 0; t < SEQ; ++t) {
        // ---- prefetch next step's inputs ----
        const int tn = (t + 1 < SEQ) ? t + 1 : t;
        float4 phn = __ldg(phB + tn*32 + lane);
        float4 e0n = __ldg(csB + tn*3 + 0), e1n = __ldg(csB + tn*3 + 1), e2n = __ldg(csB + tn*3 + 2);
        float cwn = (lane < 18) ? __ldg(cwB + tn*18 + lane) : 0.f;
        float xmn = (lane < 18) ? __ldg(angB + tn*6 + qsel) : 0.f;

        float c6[6] = {e0.x, e0.z, e1.x, e1.z, e2.x, e2.z};
        float s6[6] = {e0.y, e0.w, e1.y, e1.w, e2.y, e2.w};

        // ---- initial RY(h) product state at sigma^{-4} indices, times QSVT phase ----
        float hcv[6], hsv[6];
#pragma unroll
        for (int i = 0; i < 6; ++i) __sincosf(0.5f * h[i], &hsv[i], &hcv[i]);
        float pr0 = 1.f, pr1 = 1.f;
#pragma unroll
        for (int i = 0; i < 6; ++i) {
            pr0 *= ((s40 >> (5 - i)) & 1) ? hsv[i] : hcv[i];
            pr1 *= ((s41 >> (5 - i)) & 1) ? hsv[i] : hcv[i];
        }
        float r0 = pr0 * ph.x, i0 = pr0 * ph.y;
        float r1 = pr1 * ph.z, i1 = pr1 * ph.w;

        // ---- ansatz: 2 layers x 7 block gates ----
#pragma unroll
        for (int L = 0; L < 2; ++L) {
            applyA(r0, i0, r1, i1, 16, Aa[L], Ab[L]);     // CRX01 * T0xT1
            applyP(r0, i0, r1, i1, 8, 4, Bc[L]);          // CRX23*CRX12*T2xT3
            applyP(r0, i0, r1, i1, 2, 1, Cc[L]);          // CRX45*CRX34*T4xT5
            applyA(r0, i0, r1, i1, 2, ACa[L], ACb[L]);    // CRX54*CRX50
            applyP(r0, i0, r1, i1, 8, 4, B2c[L]);         // CRX32*CRX43
            applyA(r0, i0, r1, i1, 16, A2a[L], A2b[L]);   // CRX10*CRX21
            crx_cb5(r1, i1, 1, C5c[L], C5s[L]);           // CRX05
        }

        // ---- measurements (final RY folded via Heisenberg rotation) ----
        float w0 = r0*r0 + i0*i0;
        float w1 = r1*r1 + i1*i1;
        float ws = w0 + w1, wd = w0 - w1;
        float Zp0 = wsum(wd);
        float f = ws;
#pragma unroll
        for (int st = 0; st < 5; ++st) {
            int m = 16 >> st;
            float p = SH(f, m);
            f = (lane & m) ? (p - f) : (f + p);
        }
        float Zt[6];
        Zt[0] = Zp0;
        Zt[1] = __shfl_sync(FULLM, f, 16);
        Zt[2] = __shfl_sync(FULLM, f, 8);
        Zt[3] = __shfl_sync(FULLM, f, 4);
        Zt[4] = __shfl_sync(FULLM, f, 2);
        Zt[5] = __shfl_sync(FULLM, f, 1);

        float vr[5], vi[5];
#pragma unroll
        for (int i = 1; i <= 5; ++i) {
            int m = 1 << (5 - i);
            float pr0s = SH(r0, m), pi0s = SH(i0, m), pr1s = SH(r1, m), pi1s = SH(i1, m);
            float tr = r0*pr0s + i0*pi0s + r1*pr1s + i1*pi1s;
            float ti = r0*pi0s - i0*pr0s + r1*pi1s - i1*pr1s;
            int bit = (lane >> (5 - i)) & 1;
            vr[i-1] = bit ? 0.f : tr;
            vi[i-1] = bit ? 0.f : ti;
        }
        float zr0 = r0*r1 + i0*i1;
        float zi0 = r0*i1 - i0*r1;

        float P1, P2, P3, P4, P5, P6;
        { float a = vr[0] + SH(vr[0],16), bb = vi[0] + SH(vi[0],16); P1 = (lane&16) ? bb : a; }
        { float a = vr[1] + SH(vr[1],16), bb = vi[1] + SH(vi[1],16); P2 = (lane&16) ? bb : a; }
        { float a = vr[2] + SH(vr[2],16), bb = vi[2] + SH(vi[2],16); P3 = (lane&16) ? bb : a; }
        { float a = vr[3] + SH(vr[3],16), bb = vi[3] + SH(vi[3],16); P4 = (lane&16) ? bb : a; }
        { float a = vr[4] + SH(vr[4],16), bb = vi[4] + SH(vi[4],16); P5 = (lane&16) ? bb : a; }
        { float a = zr0   + SH(zr0,  16), bb = zi0   + SH(zi0,  16); P6 = (lane&16) ? bb : a; }
        float Q1, Q2, Q3;
        { float a = P1 + SH(P1,8), bb = P2 + SH(P2,8); Q1 = (lane&8) ? bb : a; }
        { float a = P3 + SH(P3,8), bb = P4 + SH(P4,8); Q2 = (lane&8) ? bb : a; }
        { float a = P5 + SH(P5,8), bb = P6 + SH(P6,8); Q3 = (lane&8) ? bb : a; }
        float R1, R2;
        { float a = Q1 + SH(Q1,4), bb = Q2 + SH(Q2,4); R1 = (lane&4) ? bb : a; }
        R2 = Q3 + SH(Q3,4);
        float Sv;
        { float a = R1 + SH(R1,2), bb = R2 + SH(R2,2); Sv = (lane&2) ? bb : a; }
        Sv += SH(Sv, 1);
        float zrB[6];
        zrB[0] = __shfl_sync(FULLM, Sv, 10);
        zrB[1] = __shfl_sync(FULLM, Sv, 0);
        zrB[2] = __shfl_sync(FULLM, Sv, 8);
        zrB[3] = __shfl_sync(FULLM, Sv, 4);
        zrB[4] = __shfl_sync(FULLM, Sv, 12);
        zrB[5] = __shfl_sync(FULLM, Sv, 2);
        float giZ = __shfl_sync(FULLM, Sv, srcZi);

#pragma unroll
        for (int i = 0; i < 6; ++i)
            h[i] = c6[i] * Zt[i] - s6[i] * (2.f * zrB[i]);

        float csel = SEL6(c6), ssel = SEL6(s6), zrsel = SEL6(zrB),
              ztsel = SEL6(Zt), hsel = SEL6(h);
        float mval = (lane < 6)  ? fmaf(csel, 2.f * zrsel, ssel * ztsel)
                   : (lane < 12) ? 2.f * giZ
                                 : hsel;
        if (lane < 18)
            outB[t * 18 + lane] = cwv * mval + Dme * xme;

        // rotate prefetched inputs in
        ph = phn; e0 = e0n; e1 = e1n; e2 = e2n; cwv = cwn; xme = xmn;
    }
#undef SEL6
}

// ---------------- launch ----------------
extern "C" void kernel_launch(void* const* d_in, const int* in_sizes, int n_in,
                              void* d_out, int out_size) {
    const float* angles = (const float*)d_in[0];
    const float* Wx     = (const float*)d_in[1];
    const float* Wdt    = (const float*)d_in[2];
    const float* bdt    = (const float*)d_in[3];
    const float* pc     = (const float*)d_in[4];
    const float* qp     = (const float*)d_in[5];
    const float* cp     = (const float*)d_in[6];
    const float* D      = (const float*)d_in[7];
    const float* Wc     = (const float*)d_in[8];

    prep_kernel <<<(BATCH * SEQ + 255) / 256, 256>>>(angles, Wx, Wdt, bdt, Wc);
    prep2_kernel<<<1, 64>>>(pc, qp, cp);
    prep3_kernel<<<(BATCH * SEQ * 32 + 255) / 256, 256>>>();
    sim_kernel  <<<BATCH, 32>>>(angles, D, (float*)d_out);
}

// round 12
// speedup vs baseline: 1.0764x; 1.0764x over previous
#include <cuda_runtime.h>
#include <cstdint>

#define NQ     6
#define BATCH  256
#define SEQ    512
#define FULLM  0xffffffffu
#define PI_F   3.14159265358979323846f
#define SH(v,m) __shfl_xor_sync(FULLM, (v), (m))

// ---------------- scratch ----------------
__device__ float4 g_pk [BATCH * SEQ * 3];   // [dta0..3][dta4,5,xdt0,1][xdt2..5]
__device__ float  g_cw [BATCH * SEQ * 18];
__device__ float  g_tf [24];
__device__ float2 g_fa [12];   // trio alpha (L*6+i)
__device__ float2 g_fb [12];   // trio beta
__device__ float2 g_crx[24];   // (cos,sin) half-angle: L*12 + [0..5 up][6..11 down]

// ---------------- prep 1 ----------------
__global__ void prep_kernel(const float* __restrict__ angles,
                            const float* __restrict__ Wx,
                            const float* __restrict__ Wdt,
                            const float* __restrict__ bdt,
                            const float* __restrict__ Wc) {
    int idx = blockIdx.x * blockDim.x + threadIdx.x;
    if (idx >= BATCH * SEQ) return;
    float a[6];
#pragma unroll
    for (int k = 0; k < 6; ++k) a[k] = angles[idx * 6 + k];
    float dtr[3];
#pragma unroll
    for (int r = 0; r < 3; ++r) {
        float s = 0.f;
#pragma unroll
        for (int k = 0; k < 6; ++k) s += a[k] * Wx[r * 6 + k];
        dtr[r] = s;
    }
    float C[6];
#pragma unroll
    for (int j = 0; j < 6; ++j) {
        float s = 0.f;
#pragma unroll
        for (int k = 0; k < 6; ++k) s += a[k] * Wx[(9 + j) * 6 + k];
        C[j] = s;
    }
    float dta[6];
#pragma unroll
    for (int i = 0; i < 6; ++i) {
        float v = bdt[i];
#pragma unroll
        for (int r = 0; r < 3; ++r) v += dtr[r] * Wdt[i * 3 + r];
        float sp = (v > 20.f) ? v : log1pf(expf(v));
        dta[i] = tanhf(sp) * PI_F;
    }
    g_pk[idx * 3 + 0] = make_float4(dta[0], dta[1], dta[2], dta[3]);
    g_pk[idx * 3 + 1] = make_float4(dta[4], dta[5], a[0] * dta[0], a[1] * dta[1]);
    g_pk[idx * 3 + 2] = make_float4(a[2] * dta[2], a[3] * dta[3], a[4] * dta[4], a[5] * dta[5]);
#pragma unroll
    for (int j = 0; j < 18; ++j) {
        float s = 0.f;
#pragma unroll
        for (int k = 0; k < 6; ++k) s += C[k] * Wc[j * 6 + k];
        g_cw[idx * 18 + j] = s;
    }
}

// ---------------- prep 2 ----------------
__global__ void prep2_kernel(const float* __restrict__ pc,
                             const float* __restrict__ qp,
                             const float* __restrict__ cp) {
    int t = threadIdx.x;
    if (t < 24) {
        int d = t / 6, i = t % 6;
        g_tf[t] = pc[d] * PI_F * ((d < 3) ? qp[d * 6 + i] : 1.0f);
    }
    if (t < 24) {
        int L = t / 12, k = t % 12;
        float ang = (k < 6) ? cp[L * 30 + 18 + k] : cp[L * 30 + 24 + (k - 6)];
        float th = 0.5f * ang;
        g_crx[t] = make_float2(cosf(th), sinf(th));
    }
    if (t < 12) {   // U = RZ(c)*RY(b)*RX(a), half angles
        int L = t / 6, i = t % 6, base = L * 30 + i * 3;
        float cx = cosf(0.5f * cp[base]),     sx = sinf(0.5f * cp[base]);
        float cy = cosf(0.5f * cp[base + 1]), sy = sinf(0.5f * cp[base + 1]);
        float cz = cosf(0.5f * cp[base + 2]), sz = sinf(0.5f * cp[base + 2]);
        float M00r = cy * cx, M00i = sy * sx;
        float M10r = sy * cx, M10i = -cy * sx;
        g_fa[t] = make_float2(cz * M00r + sz * M00i, cz * M00i - sz * M00r);
        g_fb[t] = make_float2(cz * M10r - sz * M10i, cz * M10i + sz * M10r);
    }
}

// ---------------- complex / matrix helpers (prologue only) ----------------
__device__ __forceinline__ float2 cmul2(float2 a, float2 b) {
    return make_float2(a.x*b.x - a.y*b.y, a.x*b.y + a.y*b.x);
}
__device__ __forceinline__ float2 cadd2(float2 a, float2 b) {
    return make_float2(a.x + b.x, a.y + b.y);
}
struct M2 { float2 m[2][2]; };
__device__ __forceinline__ M2 mkT(float2 al, float2 be) {
    M2 t;
    t.m[0][0] = al; t.m[0][1] = make_float2(-be.x, be.y);
    t.m[1][0] = be; t.m[1][1] = make_float2(al.x, -al.y);
    return t;
}
__device__ __forceinline__ M2 mkRX(float c, float s) {
    M2 t;
    t.m[0][0] = make_float2(c, 0.f); t.m[0][1] = make_float2(0.f, -s);
    t.m[1][0] = make_float2(0.f, -s); t.m[1][1] = make_float2(c, 0.f);
    return t;
}
__device__ __forceinline__ void kron4(float2 G[4][4], const M2& A, const M2& B) {
#pragma unroll
    for (int i = 0; i < 2; ++i)
#pragma unroll
    for (int j = 0; j < 2; ++j)
#pragma unroll
    for (int k = 0; k < 2; ++k)
#pragma unroll
    for (int l = 0; l < 2; ++l)
        G[2*i + k][2*j + l] = cmul2(A.m[i][j], B.m[k][l]);
}
// left-multiply by ctrl-on-HIGH gate (rows 2,3 mixed by R)
__device__ __forceinline__ void ctrlH_mul(float2 G[4][4], const M2& R) {
#pragma unroll
    for (int c = 0; c < 4; ++c) {
        float2 t2 = G[2][c], t3 = G[3][c];
        G[2][c] = cadd2(cmul2(R.m[0][0], t2), cmul2(R.m[0][1], t3));
        G[3][c] = cadd2(cmul2(R.m[1][0], t2), cmul2(R.m[1][1], t3));
    }
}
// left-multiply by R acting on HIGH qubit: mixes rows (0,2) and (1,3)
__device__ __forceinline__ void tgtH_mul(float2 G[4][4], const M2& R) {
#pragma unroll
    for (int c = 0; c < 4; ++c) {
#pragma unroll
        for (int aL = 0; aL < 2; ++aL) {
            float2 t0 = G[aL][c], t1 = G[2 + aL][c];
            G[aL][c]     = cadd2(cmul2(R.m[0][0], t0), cmul2(R.m[0][1], t1));
            G[2 + aL][c] = cadd2(cmul2(R.m[1][0], t0), cmul2(R.m[1][1], t1));
        }
    }
}
// extract A-type coeffs (H = reg bit, L = lane bit bL): rows d0, d0^2
__device__ __forceinline__ void extractA(const float2 G[4][4], int bL, float* A, float* B) {
    float2 a0 = bL ? G[1][1] : G[0][0], a1 = bL ? G[1][0] : G[0][1];
    float2 a2 = bL ? G[1][3] : G[0][2], a3 = bL ? G[1][2] : G[0][3];
    A[0]=a0.x; A[1]=a0.y; A[2]=a1.x; A[3]=a1.y; A[4]=a2.x; A[5]=a2.y; A[6]=a3.x; A[7]=a3.y;
    float2 b0 = bL ? G[3][1] : G[2][0], b1 = bL ? G[3][0] : G[2][1];
    float2 b2 = bL ? G[3][3] : G[2][2], b3 = bL ? G[3][2] : G[2][3];
    B[0]=b0.x; B[1]=b0.y; B[2]=b1.x; B[3]=b1.y; B[4]=b2.x; B[5]=b2.y; B[6]=b3.x; B[7]=b3.y;
}
// extract pair coeffs: d = 2*bH + bL; c_j = G[d][d^j]
__device__ __forceinline__ void extractP(const float2 G[4][4], int bH, int bL, float* C) {
    int d = 2*bH + bL;
#pragma unroll
    for (int j = 0; j < 4; ++j) {
        float2 c = (d == 0) ? G[0][j] : (d == 1) ? G[1][1^j] : (d == 2) ? G[2][2^j] : G[3][3^j];
        C[2*j] = c.x; C[2*j + 1] = c.y;
    }
}

// ---------------- runtime gate primitives ----------------
__device__ __forceinline__ void applyA(float& r0, float& i0, float& r1, float& i1,
                                       int mL, const float* A, const float* B) {
    float p0 = SH(r0, mL), q0 = SH(i0, mL), p1 = SH(r1, mL), q1 = SH(i1, mL);
    float nr0 = A[0]*r0 - A[1]*i0 + A[2]*p0 - A[3]*q0 + A[4]*r1 - A[5]*i1 + A[6]*p1 - A[7]*q1;
    float ni0 = A[0]*i0 + A[1]*r0 + A[2]*q0 + A[3]*p0 + A[4]*i1 + A[5]*r1 + A[6]*q1 + A[7]*p1;
    float nr1 = B[0]*r0 - B[1]*i0 + B[2]*p0 - B[3]*q0 + B[4]*r1 - B[5]*i1 + B[6]*p1 - B[7]*q1;
    float ni1 = B[0]*i0 + B[1]*r0 + B[2]*q0 + B[3]*p0 + B[4]*i1 + B[5]*r1 + B[6]*q1 + B[7]*p1;
    r0 = nr0; i0 = ni0; r1 = nr1; i1 = ni1;
}
__device__ __forceinline__ void applyP(float& r0, float& i0, float& r1, float& i1,
                                       int mH, int mL, const float* C) {
    const int mHL = mH | mL;
    float Ar0 = SH(r0, mL),  Ai0 = SH(i0, mL),  Ar1 = SH(r1, mL),  Ai1 = SH(i1, mL);
    float Br0 = SH(r0, mH),  Bi0 = SH(i0, mH),  Br1 = SH(r1, mH),  Bi1 = SH(i1, mH);
    float Cr0 = SH(r0, mHL), Ci0 = SH(i0, mHL), Cr1 = SH(r1, mHL), Ci1 = SH(i1, mHL);
    float nr0 = C[0]*r0 - C[1]*i0 + C[2]*Ar0 - C[3]*Ai0 + C[4]*Br0 - C[5]*Bi0 + C[6]*Cr0 - C[7]*Ci0;
    float ni0 = C[0]*i0 + C[1]*r0 + C[2]*Ai0 + C[3]*Ar0 + C[4]*Bi0 + C[5]*Br0 + C[6]*Ci0 + C[7]*Cr0;
    float nr1 = C[0]*r1 - C[1]*i1 + C[2]*Ar1 - C[3]*Ai1 + C[4]*Br1 - C[5]*Bi1 + C[6]*Cr1 - C[7]*Ci1;
    float ni1 = C[0]*i1 + C[1]*r1 + C[2]*Ai1 + C[3]*Ar1 + C[4]*Bi1 + C[5]*Br1 + C[6]*Ci1 + C[7]*Cr1;
    r0 = nr0; i0 = ni0; r1 = nr1; i1 = ni1;
}
__device__ __forceinline__ void crx_gen(float& r0, float& i0, float& r1, float& i1,
                                        int m, float cE, float sE) {
    float pr0 = SH(r0, m), pi0 = SH(i0, m), pr1 = SH(r1, m), pi1 = SH(i1, m);
    float nr0 = cE*r0 + sE*pi0, ni0 = cE*i0 - sE*pr0;
    float nr1 = cE*r1 + sE*pi1, ni1 = cE*i1 - sE*pr1;
    r0 = nr0; i0 = ni0; r1 = nr1; i1 = ni1;
}
__device__ __forceinline__ void crx_treg(float& r0, float& i0, float& r1, float& i1,
                                         float cE, float sE) {
    float nr0 = cE*r0 + sE*i1, ni0 = cE*i0 - sE*r1;
    float nr1 = cE*r1 + sE*i0, ni1 = cE*i1 - sE*r0;
    r0 = nr0; i0 = ni0; r1 = nr1; i1 = ni1;
}
__device__ __forceinline__ void crx_cb5(float& r1, float& i1, int m, float c, float s) {
    float p = SH(r1, m), q = SH(i1, m);
    float nr1 = fmaf(s, q, c * r1);
    float ni1 = fmaf(-s, p, c * i1);
    r1 = nr1; i1 = ni1;
}
__device__ __forceinline__ float wsum(float v) {
    v += SH(v, 16); v += SH(v, 8); v += SH(v, 4); v += SH(v, 2); v += SH(v, 1);
    return v;
}

// ---------------- main sim: one warp per chain ----------------
__global__ void __launch_bounds__(32, 1)
sim_kernel(const float* __restrict__ angles,
           const float* __restrict__ Dv_in,
           float* __restrict__ out) {
    const int b    = blockIdx.x;
    const int lane = threadIdx.x;

    // ---- composed QSVT: sigma^4 source indices + per-amp phase coefficients B ----
    int fwd[64];
    for (int s = 0; s < 64; ++s) {
        int q[6];
#pragma unroll
        for (int i = 0; i < 6; ++i) q[i] = (s >> (5 - i)) & 1;
        q[1]^=q[0]; q[2]^=q[1]; q[3]^=q[2]; q[4]^=q[3]; q[5]^=q[4];
        q[0]^=q[5]; q[4]^=q[5]; q[3]^=q[4]; q[2]^=q[3]; q[1]^=q[2]; q[0]^=q[1];
        int tt = 0;
#pragma unroll
        for (int i = 0; i < 6; ++i) tt |= q[i] << (5 - i);
        fwd[s] = tt;
    }
    int inv[64];
    for (int s = 0; s < 64; ++s) inv[fwd[s]] = s;

    float B0[6] = {0,0,0,0,0,0}, B1[6] = {0,0,0,0,0,0};
    int u0 = lane, u1 = lane + 32;
    for (int k = 1; k <= 4; ++k) {
        u0 = inv[u0]; u1 = inv[u1];
        int d = 4 - k;
#pragma unroll
        for (int i = 0; i < 6; ++i) {
            float c = 0.5f * g_tf[d * 6 + i];
            B0[i] += ((u0 >> (5 - i)) & 1) ? c : -c;
            B1[i] += ((u1 >> (5 - i)) & 1) ? c : -c;
        }
    }
    const int s40 = u0, s41 = u1;

    int lbit[5];
#pragma unroll
    for (int bp = 0; bp < 5; ++bp) lbit[bp] = (lane >> bp) & 1;
    // qubit bits: q1=lbit[4], q2=lbit[3], q3=lbit[2], q4=lbit[1], q5=lbit[0]

    // ---- build per-lane block-gate coefficients (one-time) ----
    float Aa[2][8], Ab[2][8], Bc[2][8], Cc[2][8];
    float utc[2], uts[2], dtc[2], dts[2], C5c[2], C5s[2];
    float dgc[8], dgs[8];
#pragma unroll
    for (int L = 0; L < 2; ++L) {
        M2 T0 = mkT(g_fa[L*6+0], g_fb[L*6+0]);
        M2 T1 = mkT(g_fa[L*6+1], g_fb[L*6+1]);
        M2 T2 = mkT(g_fa[L*6+2], g_fb[L*6+2]);
        M2 T3 = mkT(g_fa[L*6+3], g_fb[L*6+3]);
        M2 T4 = mkT(g_fa[L*6+4], g_fb[L*6+4]);
        M2 T5 = mkT(g_fa[L*6+5], g_fb[L*6+5]);
        float2 cs;
        cs = g_crx[L*12+0];  M2 R01 = mkRX(cs.x, cs.y);
        cs = g_crx[L*12+1];  M2 R12c = mkRX(lbit[4] ? cs.x : 1.f, lbit[4] ? cs.y : 0.f);
        cs = g_crx[L*12+2];  M2 R23 = mkRX(cs.x, cs.y);
        cs = g_crx[L*12+3];  M2 R34c = mkRX(lbit[2] ? cs.x : 1.f, lbit[2] ? cs.y : 0.f);
        cs = g_crx[L*12+4];  M2 R45 = mkRX(cs.x, cs.y);
        cs = g_crx[L*12+5];  { int p = lbit[0]; utc[L] = p ? cs.x : 1.f; uts[L] = p ? cs.y : 0.f; }
#pragma unroll
        for (int j = 0; j < 4; ++j) {   // down-ring generals: ctrl bp j, tgt mask 2<<j
            float2 c2 = g_crx[L*12 + 6 + j]; int p = lbit[j];
            dgc[L*4 + j] = p ? c2.x : 1.f;  dgs[L*4 + j] = p ? c2.y : 0.f;
        }
        cs = g_crx[L*12+10]; { int p = lbit[4]; dtc[L] = p ? cs.x : 1.f; dts[L] = p ? cs.y : 0.f; }
        cs = g_crx[L*12+11]; C5c[L] = cs.x; C5s[L] = cs.y;

        float2 G[4][4];
        // A = CRX(0,1) * (T0 x T1) on (q0=reg H, q1=m16 L)
        kron4(G, T0, T1); ctrlH_mul(G, R01);
        extractA(G, lbit[4], Aa[L], Ab[L]);
        // B = CRX(2,3) * CRX(1,2)|q1 * (T2 x T3) on (q2=m8 H, q3=m4 L)
        kron4(G, T2, T3); tgtH_mul(G, R12c); ctrlH_mul(G, R23);
        extractP(G, lbit[3], lbit[2], Bc[L]);
        // C = CRX(4,5) * CRX(3,4)|q3 * (T4 x T5) on (q4=m2 H, q5=m1 L)
        kron4(G, T4, T5); tgtH_mul(G, R34c); ctrlH_mul(G, R45);
        extractP(G, lbit[1], lbit[0], Cc[L]);
    }

    // zi gather lanes + qubit-select predicates
    int srcZi = 26;
    if (lane == 7)  srcZi = 16;
    if (lane == 8)  srcZi = 24;
    if (lane == 9)  srcZi = 20;
    if (lane == 10) srcZi = 28;
    if (lane == 11) srcZi = 18;
    const int qsel = lane % 6;
    const bool q0 = qsel == 0, q1 = qsel == 1, q2 = qsel == 2, q3 = qsel == 3, q4 = qsel == 4;
#define SEL6(v) (q0 ? v[0] : q1 ? v[1] : q2 ? v[2] : q3 ? v[3] : q4 ? v[4] : v[5])

    float h[6] = {0.f, 0.f, 0.f, 0.f, 0.f, 0.f};
    const float*  angB = angles + (size_t)b * SEQ * 6;
    const float4* pkB  = g_pk   + (size_t)b * SEQ * 3;
    const float*  cwB  = g_cw   + (size_t)b * SEQ * 18;
    float*        outB = out    + (size_t)b * SEQ * 18;
    const float   Dme  = (lane < 18) ? Dv_in[lane] : 0.f;

    // preload t=0 inputs
    float4 f0 = __ldg(pkB + 0), f1 = __ldg(pkB + 1), f2 = __ldg(pkB + 2);
    float cwv = (lane < 18) ? __ldg(cwB + lane) : 0.f;
    float xme = (lane < 18) ? __ldg(angB + qsel) : 0.f;

#pragma unroll 1
    for (int t = 0; t < SEQ; ++t) {
        // ---- prefetch next step's inputs ----
        const int tn = (t + 1 < SEQ) ? t + 1 : t;
        float4 f0n = __ldg(pkB + tn*3 + 0), f1n = __ldg(pkB + tn*3 + 1), f2n = __ldg(pkB + tn*3 + 2);
        float cwn = (lane < 18) ? __ldg(cwB + tn*18 + lane) : 0.f;
        float xmn = (lane < 18) ? __ldg(angB + tn*6 + qsel) : 0.f;

        float dta[6] = {f0.x, f0.y, f0.z, f0.w, f1.x, f1.y};
        float xdt[6] = {f1.z, f1.w, f2.x, f2.y, f2.z, f2.w};

        // ---- h-independent math: QSVT phase + fold sincos ----
        float acc0 = B0[0] * dta[0], acc1 = B1[0] * dta[0];
#pragma unroll
        for (int i = 1; i < 6; ++i) {
            acc0 = fmaf(B0[i], dta[i], acc0);
            acc1 = fmaf(B1[i], dta[i], acc1);
        }
        float c0, s0, c1, s1;
        __sincosf(acc0, &s0, &c0);
        __sincosf(acc1, &s1, &c1);
        float c6[6], s6[6];
#pragma unroll
        for (int i = 0; i < 6; ++i) __sincosf(xdt[i], &s6[i], &c6[i]);

        // ---- initial RY(h) product state at sigma^{-4} indices, times QSVT phase ----
        float hcv[6], hsv[6];
#pragma unroll
        for (int i = 0; i < 6; ++i) __sincosf(0.5f * h[i], &hsv[i], &hcv[i]);
        float pr0 = 1.f, pr1 = 1.f;
#pragma unroll
        for (int i = 0; i < 6; ++i) {
            pr0 *= ((s40 >> (5 - i)) & 1) ? hsv[i] : hcv[i];
            pr1 *= ((s41 >> (5 - i)) & 1) ? hsv[i] : hcv[i];
        }
        float r0 = pr0 * c0, i0 = pr0 * s0;
        float r1 = pr1 * c1, i1 = pr1 * s1;

        // ---- ansatz: 2 layers: A, B, C fused blocks + scalar down-ring ----
#pragma unroll
        for (int L = 0; L < 2; ++L) {
            applyA(r0, i0, r1, i1, 16, Aa[L], Ab[L]);      // CRX01 * T0xT1
            applyP(r0, i0, r1, i1, 8, 4, Bc[L]);           // CRX23*CRX12*T2xT3
            applyP(r0, i0, r1, i1, 2, 1, Cc[L]);           // CRX45*CRX34*T4xT5
            crx_treg(r0, i0, r1, i1, utc[L], uts[L]);      // CRX(5,0)
            crx_gen(r0, i0, r1, i1, 2,  dgc[L*4+0], dgs[L*4+0]);  // CRX(5,4)
            crx_gen(r0, i0, r1, i1, 4,  dgc[L*4+1], dgs[L*4+1]);  // CRX(4,3)
            crx_gen(r0, i0, r1, i1, 8,  dgc[L*4+2], dgs[L*4+2]);  // CRX(3,2)
            crx_gen(r0, i0, r1, i1, 16, dgc[L*4+3], dgs[L*4+3]);  // CRX(2,1)
            crx_treg(r0, i0, r1, i1, dtc[L], dts[L]);      // CRX(1,0)
            crx_cb5(r1, i1, 1, C5c[L], C5s[L]);            // CRX(0,5)
        }

        // ---- measurements (final RY folded via Heisenberg rotation) ----
        float w0 = r0*r0 + i0*i0;
        float w1 = r1*r1 + i1*i1;
        float ws = w0 + w1, wd = w0 - w1;
        float Zp0 = wsum(wd);
        float f = ws;
#pragma unroll
        for (int st = 0; st < 5; ++st) {
            int m = 16 >> st;
            float p = SH(f, m);
            f = (lane & m) ? (p - f) : (f + p);
        }
        float Zt[6];
        Zt[0] = Zp0;
        Zt[1] = __shfl_sync(FULLM, f, 16);
        Zt[2] = __shfl_sync(FULLM, f, 8);
        Zt[3] = __shfl_sync(FULLM, f, 4);
        Zt[4] = __shfl_sync(FULLM, f, 2);
        Zt[5] = __shfl_sync(FULLM, f, 1);

        float vr[5], vi[5];
#pragma unroll
        for (int i = 1; i <= 5; ++i) {
            int m = 1 << (5 - i);
            float pr0s = SH(r0, m), pi0s = SH(i0, m), pr1s = SH(r1, m), pi1s = SH(i1, m);
            float tr = r0*pr0s + i0*pi0s + r1*pr1s + i1*pi1s;
            float ti = r0*pi0s - i0*pr0s + r1*pi1s - i1*pr1s;
            int bit = (lane >> (5 - i)) & 1;
            vr[i-1] = bit ? 0.f : tr;
            vi[i-1] = bit ? 0.f : ti;
        }
        float zr0 = r0*r1 + i0*i1;
        float zi0 = r0*i1 - i0*r1;

        float P1, P2, P3, P4, P5, P6;
        { float a = vr[0] + SH(vr[0],16), bb = vi[0] + SH(vi[0],16); P1 = (lane&16) ? bb : a; }
        { float a = vr[1] + SH(vr[1],16), bb = vi[1] + SH(vi[1],16); P2 = (lane&16) ? bb : a; }
        { float a = vr[2] + SH(vr[2],16), bb = vi[2] + SH(vi[2],16); P3 = (lane&16) ? bb : a; }
        { float a = vr[3] + SH(vr[3],16), bb = vi[3] + SH(vi[3],16); P4 = (lane&16) ? bb : a; }
        { float a = vr[4] + SH(vr[4],16), bb = vi[4] + SH(vi[4],16); P5 = (lane&16) ? bb : a; }
        { float a = zr0   + SH(zr0,  16), bb = zi0   + SH(zi0,  16); P6 = (lane&16) ? bb : a; }
        float Q1, Q2, Q3;
        { float a = P1 + SH(P1,8), bb = P2 + SH(P2,8); Q1 = (lane&8) ? bb : a; }
        { float a = P3 + SH(P3,8), bb = P4 + SH(P4,8); Q2 = (lane&8) ? bb : a; }
        { float a = P5 + SH(P5,8), bb = P6 + SH(P6,8); Q3 = (lane&8) ? bb : a; }
        float R1, R2;
        { float a = Q1 + SH(Q1,4), bb = Q2 + SH(Q2,4); R1 = (lane&4) ? bb : a; }
        R2 = Q3 + SH(Q3,4);
        float Sv;
        { float a = R1 + SH(R1,2), bb = R2 + SH(R2,2); Sv = (lane&2) ? bb : a; }
        Sv += SH(Sv, 1);
        float zrB[6];
        zrB[0] = __shfl_sync(FULLM, Sv, 10);
        zrB[1] = __shfl_sync(FULLM, Sv, 0);
        zrB[2] = __shfl_sync(FULLM, Sv, 8);
        zrB[3] = __shfl_sync(FULLM, Sv, 4);
        zrB[4] = __shfl_sync(FULLM, Sv, 12);
        zrB[5] = __shfl_sync(FULLM, Sv, 2);
        float giZ = __shfl_sync(FULLM, Sv, srcZi);

#pragma unroll
        for (int i = 0; i < 6; ++i)
            h[i] = c6[i] * Zt[i] - s6[i] * (2.f * zrB[i]);

        float csel = SEL6(c6), ssel = SEL6(s6), zrsel = SEL6(zrB),
              ztsel = SEL6(Zt), hsel = SEL6(h);
        float mval = (lane < 6)  ? fmaf(csel, 2.f * zrsel, ssel * ztsel)
                   : (lane < 12) ? 2.f * giZ
                                 : hsel;
        if (lane < 18)
            outB[t * 18 + lane] = cwv * mval + Dme * xme;

        // rotate prefetched inputs in
        f0 = f0n; f1 = f1n; f2 = f2n; cwv = cwn; xme = xmn;
    }
#undef SEL6
}

// ---------------- launch ----------------
extern "C" void kernel_launch(void* const* d_in, const int* in_sizes, int n_in,
                              void* d_out, int out_size) {
    const float* angles = (const float*)d_in[0];
    const float* Wx     = (const float*)d_in[1];
    const float* Wdt    = (const float*)d_in[2];
    const float* bdt    = (const float*)d_in[3];
    const float* pc     = (const float*)d_in[4];
    const float* qp     = (const float*)d_in[5];
    const float* cp     = (const float*)d_in[6];
    const float* D      = (const float*)d_in[7];
    const float* Wc     = (const float*)d_in[8];

    prep_kernel <<<(BATCH * SEQ + 255) / 256, 256>>>(angles, Wx, Wdt, bdt, Wc);
    prep2_kernel<<<1, 64>>>(pc, qp, cp);
    sim_kernel  <<<BATCH, 32>>>(angles, D, (float*)d_out);
}